// round 16
// baseline (speedup 1.0000x reference)
#include <cuda_runtime.h>
#include <cuda_bf16.h>
#include <cstdint>

#define A_N 50000
#define E_N 1200000
#define T_N 2000000
#define G_N 500
#define U_N 64
#define RBF_N 48
#define NTILE2 (E_N / 64)            // 18750 tiles of 64 bonds
#define NBLK_E ((E_N + 255) / 256)   // 4688

// ---------------- scratch (device globals; no allocation allowed) ----------------
__device__ float g_atom[A_N * U_N];
__device__ float g_bond[E_N * U_N];
__device__ float g_tuw[A_N * RBF_N];
__device__ float g_agg[E_N * RBF_N];
__device__ float g_Psrc[A_N * 128];   // interleaved {P1s,P2s} per u
__device__ float g_Pdst[A_N * 128];   // interleaved {P1d,P2d} per u
__device__ float g_num[G_N * U_N];
__device__ float g_cnt[G_N];
// W fragments: [ks_global 0..10][tid 0..255][8 words]; base: tf=0, gb=3, ga=7
__device__ uint32_t g_wfrag[11 * 256 * 8];
// CSR for triples grouped by bond (static across the 3 blocks)
__device__ int  g_deg[E_N];
__device__ int  g_basei[E_N];
__device__ int  g_cur[E_N];
__device__ int  g_blks[NBLK_E];
__device__ int2 g_csr[T_N];          // {triple_idx, end_atom}

__device__ __forceinline__ float sigm(float x) { return 1.0f / (1.0f + __expf(-x)); }
__device__ __forceinline__ float silu_f(float x) { return x * sigm(x); }

__device__ __forceinline__ void red_add_v2(float* addr, float a, float b) {
    asm volatile("red.global.add.v2.f32 [%0], {%1,%2};"
                 :: "l"(addr), "f"(a), "f"(b) : "memory");
}
__device__ __forceinline__ void red_add_v4(float* addr, float a, float b, float c, float d) {
    asm volatile("red.global.add.v4.f32 [%0], {%1,%2,%3,%4};"
                 :: "l"(addr), "f"(a), "f"(b), "f"(c), "f"(d) : "memory");
}

// ---------------- warp-MMA helpers ----------------
__device__ __forceinline__ uint32_t smem_u32(const void* p) {
    uint32_t a;
    asm("{ .reg .u64 t; cvta.to.shared.u64 t, %1; cvt.u32.u64 %0, t; }" : "=r"(a) : "l"(p));
    return a;
}
#define SWZ(x) ((x) ^ (((x) >> 3) & 0x70))

__device__ __forceinline__ void ldsm4(uint32_t* r, uint32_t a) {
    asm volatile("ldmatrix.sync.aligned.m8n8.x4.shared.b16 {%0,%1,%2,%3}, [%4];"
        : "=r"(r[0]), "=r"(r[1]), "=r"(r[2]), "=r"(r[3]) : "r"(a));
}
__device__ __forceinline__ void mma_bf16(float* d, const uint32_t* a, const uint32_t* b) {
    asm volatile("mma.sync.aligned.m16n8k16.row.col.f32.bf16.bf16.f32 "
        "{%0,%1,%2,%3}, {%4,%5,%6,%7}, {%8,%9}, {%0,%1,%2,%3};"
        : "+f"(d[0]), "+f"(d[1]), "+f"(d[2]), "+f"(d[3])
        : "r"(a[0]), "r"(a[1]), "r"(a[2]), "r"(a[3]), "r"(b[0]), "r"(b[1]));
}

__device__ __forceinline__ void split2(float x, float y, uint32_t& hw, uint32_t& lw) {
    __nv_bfloat16 hx = __float2bfloat16(x), hy = __float2bfloat16(y);
    __nv_bfloat16 lx = __float2bfloat16(x - __bfloat162float(hx));
    __nv_bfloat16 ly = __float2bfloat16(y - __bfloat162float(hy));
    __nv_bfloat162 h2 = __halves2bfloat162(hx, hy), l2 = __halves2bfloat162(lx, ly);
    hw = *(uint32_t*)&h2; lw = *(uint32_t*)&l2;
}
__device__ __forceinline__ void split_store(char* bh, char* bl, uint32_t byteoff, float x, float y) {
    uint32_t hw, lw;
    split2(x, y, hw, lw);
    uint32_t so = SWZ(byteoff);
    *(uint32_t*)(bh + so) = hw;
    *(uint32_t*)(bl + so) = lw;
}
__device__ __forceinline__ float2 merge_hl(uint32_t hw, uint32_t lw) {
    __nv_bfloat162 h = *(__nv_bfloat162*)&hw, l = *(__nv_bfloat162*)&lw;
    return make_float2(__bfloat162float(h.x) + __bfloat162float(l.x),
                       __bfloat162float(h.y) + __bfloat162float(l.y));
}

// MMA for a pair of 16-row m-tiles; W streamed per-kstep from global (L1-resident table).
template<int NKS>
__device__ __forceinline__ void gemm_pair2(
    float* D1a, float* D2a, float* D1b, float* D2b,
    uint32_t xh, uint32_t xl, int ma, int lane,
    const uint32_t* __restrict__ wptr)
{
    int mtx = lane >> 3, rr = lane & 7;
    int rowa = 16 * ma + rr + 8 * (mtx & 1);
    int rowb = rowa + 16;
    int cb = (mtx >> 1) * 16;
#pragma unroll
    for (int ks = 0; ks < NKS; ks++) {
        uint4 wa = __ldg((const uint4*)(wptr + ks * 2048));
        uint4 wb = __ldg((const uint4*)(wptr + ks * 2048 + 4));
        uint32_t W1h[2] = {wa.x, wa.y}, W1l[2] = {wa.z, wa.w};
        uint32_t W2h[2] = {wb.x, wb.y}, W2l[2] = {wb.z, wb.w};
        uint32_t oa = SWZ((uint32_t)(rowa * 128 + ks * 32 + cb));
        uint32_t ob = SWZ((uint32_t)(rowb * 128 + ks * 32 + cb));
        uint32_t Aha[4], Ala[4], Ahb[4], Alb[4];
        ldsm4(Aha, xh + oa); ldsm4(Ahb, xh + ob);
        ldsm4(Ala, xl + oa); ldsm4(Alb, xl + ob);
        mma_bf16(D1a, Aha, W1h); mma_bf16(D1b, Ahb, W1h);
        mma_bf16(D2a, Aha, W2h); mma_bf16(D2b, Ahb, W2h);
        mma_bf16(D1a, Ala, W1h); mma_bf16(D1b, Alb, W1h);
        mma_bf16(D2a, Ala, W2h); mma_bf16(D2b, Alb, W2h);
        mma_bf16(D1a, Aha, W1l); mma_bf16(D1b, Ahb, W1l);
        mma_bf16(D2a, Aha, W2l); mma_bf16(D2b, Ahb, W2l);
    }
}

// ---------------- mega init ----------------
#define NB_ATOM  ((A_N * U_N + 255) / 256)
#define NB_BOND  ((E_N * U_N + 255) / 256)
#define NB_AGG   ((E_N * RBF_N / 4 + 255) / 256)
#define NB_INIT  (NB_ATOM + NB_BOND + NB_AGG + NBLK_E + 1)

__global__ void k_init_mega(const int* __restrict__ types, const float* __restrict__ emb,
                            const float* __restrict__ rbf, const float* __restrict__ W,
                            const float* __restrict__ b) {
    int blk = blockIdx.x;
    if (blk < NB_ATOM) {
        int idx = blk * 256 + threadIdx.x;
        if (idx >= A_N * U_N) return;
        int a = idx >> 6, u = idx & 63;
        g_atom[idx] = __ldg(&emb[__ldg(&types[a]) * U_N + u]);
        return;
    }
    blk -= NB_ATOM;
    if (blk < NB_BOND) {
        int idx = blk * 256 + threadIdx.x;
        if (idx >= E_N * U_N) return;
        int e = idx >> 6, u = idx & 63;
        float v = __ldg(&b[u]);
        v += __ldg(&rbf[e * 3 + 0]) * __ldg(&W[0 * U_N + u]);
        v += __ldg(&rbf[e * 3 + 1]) * __ldg(&W[1 * U_N + u]);
        v += __ldg(&rbf[e * 3 + 2]) * __ldg(&W[2 * U_N + u]);
        g_bond[idx] = silu_f(v);
        return;
    }
    blk -= NB_BOND;
    if (blk < NB_AGG) {
        int idx = blk * 256 + threadIdx.x;
        if (idx < E_N * RBF_N / 4)
            ((float4*)g_agg)[idx] = make_float4(0.f, 0.f, 0.f, 0.f);
        return;
    }
    blk -= NB_AGG;
    if (blk < NBLK_E) {
        int idx = blk * 256 + threadIdx.x;
        if (idx < E_N) g_deg[idx] = 0;
        return;
    }
    for (int idx = threadIdx.x; idx < G_N * U_N; idx += 256) g_num[idx] = 0.f;
    for (int idx = threadIdx.x; idx < G_N; idx += 256) g_cnt[idx] = 0.f;
}

// ---------------- prep bodies ----------------
__device__ __forceinline__ void tu_body(int idx, const float* tuW, const float* tub) {
    if (idx >= A_N * RBF_N) return;
    int a = idx / RBF_N, j = idx - a * RBF_N;
    const float* arow = g_atom + a * U_N;
    float s = __ldg(&tub[j]);
#pragma unroll 8
    for (int k = 0; k < U_N; k++) s += arow[k] * __ldg(&tuW[k * RBF_N + j]);
    g_tuw[idx] = sigm(s);
}
__device__ __forceinline__ void P_body(int idx, const float* W1, const float* W2) {
    if (idx >= A_N * U_N) return;
    int a = idx >> 6, u = idx & 63;
    const float* arow = g_atom + a * U_N;
    float s0 = 0.f, s1 = 0.f, s2 = 0.f, s3 = 0.f;
#pragma unroll 8
    for (int k = 0; k < U_N; k++) {
        float av = arow[k];
        s0 += av * __ldg(&W1[k * U_N + u]);
        s1 += av * __ldg(&W1[(U_N + k) * U_N + u]);
        s2 += av * __ldg(&W2[k * U_N + u]);
        s3 += av * __ldg(&W2[(U_N + k) * U_N + u]);
    }
    g_Psrc[a * 128 + 2 * u]     = s0;
    g_Psrc[a * 128 + 2 * u + 1] = s2;
    g_Pdst[a * 128 + 2 * u]     = s1;
    g_Pdst[a * 128 + 2 * u + 1] = s3;
}
__device__ __forceinline__ void wprep_body(int s, int tid,
                        const float* tfW1, const float* tfW2,
                        const float* gbW1c, const float* gbW2c,
                        const float* gaW1, const float* gaW2) {
    int wid = tid >> 5, lane = tid & 31;
    int q = lane & 3, nf = lane >> 2;
    int n_abs = 8 * wid + nf;
    const float *W1, *W2; int nks, base;
    if (s == 0)      { W1 = tfW1;  W2 = tfW2;  nks = 3; base = 0; }
    else if (s == 1) { W1 = gbW1c; W2 = gbW2c; nks = 4; base = 3; }
    else             { W1 = gaW1;  W2 = gaW2;  nks = 4; base = 7; }
    for (int m = 0; m < 2; m++) {
        const float* W = m ? W2 : W1;
        for (int ks = 0; ks < nks; ks++)
            for (int R = 0; R < 2; R++) {
                int k0 = 16 * ks + 2 * q + 8 * R;
                float x = __ldg(&W[k0 * 64 + n_abs]);
                float y = __ldg(&W[(k0 + 1) * 64 + n_abs]);
                uint32_t hw, lw;
                split2(x, y, hw, lw);
                uint32_t* slot = g_wfrag + ((base + ks) * 256 + tid) * 8;
                slot[m * 4 + R]     = hw;
                slot[m * 4 + 2 + R] = lw;
            }
    }
}

#define NB_TU ((A_N * RBF_N + 255) / 256)
#define NB_P  ((A_N * U_N + 255) / 256)

__global__ void k_prep_mega(const float* __restrict__ tuW, const float* __restrict__ tub,
                            const float* __restrict__ gbW1, const float* __restrict__ gbW2,
                            const float* __restrict__ tfW1, const float* __restrict__ tfW2,
                            const float* __restrict__ gaW1, const float* __restrict__ gaW2) {
    int blk = blockIdx.x;
    if (blk < NB_TU) { tu_body(blk * 256 + threadIdx.x, tuW, tub); return; }
    blk -= NB_TU;
    if (blk < NB_P) { P_body(blk * 256 + threadIdx.x, gbW1, gbW2); return; }
    blk -= NB_P;
    wprep_body(blk, threadIdx.x, tfW1, tfW2, gbW1 + 128 * U_N, gbW2 + 128 * U_N, gaW1, gaW2);
}

__global__ void k_tu(const float* __restrict__ tuW, const float* __restrict__ tub) {
    tu_body(blockIdx.x * blockDim.x + threadIdx.x, tuW, tub);
}
__global__ void k_P(const float* __restrict__ W1, const float* __restrict__ W2) {
    P_body(blockIdx.x * blockDim.x + threadIdx.x, W1, W2);
}
__global__ void k_wprep(const float* __restrict__ tfW1, const float* __restrict__ tfW2,
                        const float* __restrict__ gbW1c, const float* __restrict__ gbW2c,
                        const float* __restrict__ gaW1, const float* __restrict__ gaW2) {
    wprep_body(blockIdx.x, threadIdx.x, tfW1, tfW2, gbW1c, gbW2c, gaW1, gaW2);
}

// ---------------- iter-0 triples: atomic scatter ----------------
__global__ void k_triples(const float4* __restrict__ tb, const int2* __restrict__ tbi,
                          const int2* __restrict__ bai) {
    int idx = blockIdx.x * blockDim.x + threadIdx.x;
    if (idx >= T_N * 12) return;
    int t = idx / 12, c = idx - t * 12;
    int2 ti = __ldg(&tbi[t]);
    int ea = __ldg(&bai[ti.y]).y;
    float4 tv = __ldg(&tb[t * 12 + c]);
    float4 wv = __ldg((const float4*)(g_tuw + ea * RBF_N + c * 4));
    red_add_v4(g_agg + ti.x * RBF_N + c * 4,
               tv.x * wv.x, tv.y * wv.y, tv.z * wv.z, tv.w * wv.w);
}

// ---------------- CSR build ----------------
__global__ void k_count(const int2* __restrict__ tbi) {
    int t = blockIdx.x * blockDim.x + threadIdx.x;
    if (t < T_N) atomicAdd(&g_deg[__ldg(&tbi[t]).x], 1);
}
__global__ void k_scanA() {
    __shared__ int ssum[256];
    int idx = blockIdx.x * 256 + threadIdx.x;
    int v = (idx < E_N) ? g_deg[idx] : 0;
    ssum[threadIdx.x] = v;
    __syncthreads();
    for (int off = 128; off > 0; off >>= 1) {
        if (threadIdx.x < off) ssum[threadIdx.x] += ssum[threadIdx.x + off];
        __syncthreads();
    }
    if (threadIdx.x == 0) g_blks[blockIdx.x] = ssum[0];
}
__global__ void k_scanB() {
    __shared__ int wsum[8];
    const int CH = (NBLK_E + 255) / 256;
    int tid = threadIdx.x, lane = tid & 31, wid = tid >> 5;
    int vals[CH];
    int s = 0;
#pragma unroll
    for (int j = 0; j < CH; j++) {
        int i = tid * CH + j;
        vals[j] = (i < NBLK_E) ? g_blks[i] : 0;
        s += vals[j];
    }
    int incl = s;
    for (int off = 1; off < 32; off <<= 1) {
        int n = __shfl_up_sync(0xFFFFFFFFu, incl, off);
        if (lane >= off) incl += n;
    }
    if (lane == 31) wsum[wid] = incl;
    __syncthreads();
    int woff = 0;
    for (int w = 0; w < 8; w++) { if (w < wid) woff += wsum[w]; }
    int run = woff + incl - s;
#pragma unroll
    for (int j = 0; j < CH; j++) {
        int i = tid * CH + j;
        if (i < NBLK_E) { g_blks[i] = run; }
        run += vals[j];
    }
}
__global__ void k_scanC() {
    __shared__ int wsum[8];
    int idx = blockIdx.x * 256 + threadIdx.x;
    int tid = threadIdx.x, lane = tid & 31, wid = tid >> 5;
    int v = (idx < E_N) ? g_deg[idx] : 0;
    int incl = v;
    for (int off = 1; off < 32; off <<= 1) {
        int n = __shfl_up_sync(0xFFFFFFFFu, incl, off);
        if (lane >= off) incl += n;
    }
    if (lane == 31) wsum[wid] = incl;
    __syncthreads();
    int woff = 0;
    for (int w = 0; w < 8; w++) { if (w < wid) woff += wsum[w]; }
    if (idx < E_N) {
        g_basei[idx] = g_blks[blockIdx.x] + woff + incl - v;
        g_cur[idx] = 0;
    }
}
__global__ void k_fill(const int2* __restrict__ tbi, const int2* __restrict__ bai) {
    int t = blockIdx.x * blockDim.x + threadIdx.x;
    if (t >= T_N) return;
    int2 ti = __ldg(&tbi[t]);
    int ea = __ldg(&bai[ti.y]).y;
    int pos = g_basei[ti.x] + atomicAdd(&g_cur[ti.x], 1);
    g_csr[pos] = make_int2(t, ea);
}

// gather triple segment-sum: 4 threads per bond (iters 1,2)
__global__ void k_agg(const float4* __restrict__ tb) {
    int idx = blockIdx.x * blockDim.x + threadIdx.x;
    if (idx >= E_N * 4) return;
    int e = idx >> 2, q = idx & 3;
    int b0 = __ldg(&g_basei[e]);
    int b1 = (e == E_N - 1) ? T_N : __ldg(&g_basei[e + 1]);
    float4 a0 = make_float4(0.f, 0.f, 0.f, 0.f), a1 = a0, a2 = a0;
    for (int p = b0; p < b1; p++) {
        int2 te = __ldg(&g_csr[p]);
        const float4* tvp = tb + (size_t)te.x * 12 + q * 3;
        const float4* wvp = (const float4*)(g_tuw + (size_t)te.y * RBF_N + q * 12);
        float4 t0 = __ldg(tvp),     w0 = __ldg(wvp);
        float4 t1 = __ldg(tvp + 1), w1 = __ldg(wvp + 1);
        float4 t2 = __ldg(tvp + 2), w2 = __ldg(wvp + 2);
        a0.x += t0.x * w0.x; a0.y += t0.y * w0.y; a0.z += t0.z * w0.z; a0.w += t0.w * w0.w;
        a1.x += t1.x * w1.x; a1.y += t1.y * w1.y; a1.z += t1.z * w1.z; a1.w += t1.w * w1.w;
        a2.x += t2.x * w2.x; a2.y += t2.y * w2.y; a2.z += t2.z * w2.z; a2.w += t2.w * w2.w;
    }
    float4* dst = (float4*)(g_agg + (size_t)e * RBF_N + q * 12);
    dst[0] = a0; dst[1] = a1; dst[2] = a2;
}

// ---------------- tensor-core fused bond kernel: M=64 tiles, 4 CTAs/SM ----------------
#define SM_XAH 0
#define SM_XAL 8192
#define SM_XBH 16384
#define SM_XBL 24576
#define SM_X2H 32768
#define SM_X2L 40960
#define SM_BAI 49152
#define SM_TOT (49152 + 1024)

#define EPI_A(M, D1, D2) { \
    int rA = 16 * (M) + r0, rB = rA + 8; \
    int eA = e0 + rA, eB = e0 + rB; \
    float2 v0 = __ldg((const float2*)(g_bond + (size_t)eA * 64 + u0)); \
    float2 v1 = __ldg((const float2*)(g_bond + (size_t)eB * 64 + u0)); \
    float n0 = v0.x + silu_f((D1)[0] + tb1a) * sigm((D2)[0] + tb2a); \
    float n1 = v0.y + silu_f((D1)[1] + tb1b) * sigm((D2)[1] + tb2b); \
    float n2 = v1.x + silu_f((D1)[2] + tb1a) * sigm((D2)[2] + tb2a); \
    float n3 = v1.y + silu_f((D1)[3] + tb1b) * sigm((D2)[3] + tb2b); \
    split_store(XBHp, XBLp, (uint32_t)(rA * 128 + u0 * 2), n0, n1); \
    split_store(XBHp, XBLp, (uint32_t)(rB * 128 + u0 * 2), n2, n3); \
}

#define EPI_B(M, D1, D2) { \
    int rA = 16 * (M) + r0, rB = rA + 8; \
    int eA = e0 + rA, eB = e0 + rB; \
    uint32_t offA = SWZ((uint32_t)(rA * 128 + u0 * 2)); \
    uint32_t offB = SWZ((uint32_t)(rB * 128 + u0 * 2)); \
    float2 resA = merge_hl(*(uint32_t*)(XBHp + offA), *(uint32_t*)(XBLp + offA)); \
    float2 resB = merge_hl(*(uint32_t*)(XBHp + offB), *(uint32_t*)(XBLp + offB)); \
    int2 iA = s_bai[rA]; int2 iB = s_bai[rB]; \
    float4 psA = __ldg((const float4*)(g_Psrc + (size_t)iA.x * 128 + 2 * u0)); \
    float4 pdA = __ldg((const float4*)(g_Pdst + (size_t)iA.y * 128 + 2 * u0)); \
    float4 psB = __ldg((const float4*)(g_Psrc + (size_t)iB.x * 128 + 2 * u0)); \
    float4 pdB = __ldg((const float4*)(g_Pdst + (size_t)iB.y * 128 + 2 * u0)); \
    float n0 = resA.x + silu_f((D1)[0] + gb1a + psA.x + pdA.x) * sigm((D2)[0] + gb2a + psA.y + pdA.y); \
    float n1 = resA.y + silu_f((D1)[1] + gb1b + psA.z + pdA.z) * sigm((D2)[1] + gb2b + psA.w + pdA.w); \
    float n2 = resB.x + silu_f((D1)[2] + gb1a + psB.x + pdB.x) * sigm((D2)[2] + gb2a + psB.y + pdB.y); \
    float n3 = resB.y + silu_f((D1)[3] + gb1b + psB.z + pdB.z) * sigm((D2)[3] + gb2b + psB.w + pdB.w); \
    *(float2*)(g_bond + (size_t)eA * 64 + u0) = make_float2(n0, n1); \
    *(float2*)(g_bond + (size_t)eB * 64 + u0) = make_float2(n2, n3); \
    split_store(X2Hp, X2Lp, (uint32_t)(rA * 128 + u0 * 2), n0, n1); \
    split_store(X2Hp, X2Lp, (uint32_t)(rB * 128 + u0 * 2), n2, n3); \
}

#define EPI_C(M, D1, D2) { \
    int rA = 16 * (M) + r0, rB = rA + 8; \
    int dA = s_bai[rA].y, dB = s_bai[rB].y; \
    float m0 = silu_f((D1)[0] + ga1a) * sigm((D2)[0] + ga2a); \
    float m1 = silu_f((D1)[1] + ga1b) * sigm((D2)[1] + ga2b); \
    float m2 = silu_f((D1)[2] + ga1a) * sigm((D2)[2] + ga2a); \
    float m3 = silu_f((D1)[3] + ga1b) * sigm((D2)[3] + ga2b); \
    red_add_v2(g_atom + (size_t)dA * 64 + u0, m0, m1); \
    red_add_v2(g_atom + (size_t)dB * 64 + u0, m2, m3); \
}

__global__ __launch_bounds__(256, 4) void k_bond_tc(
    const int2* __restrict__ bai,
    const float* __restrict__ tfb1, const float* __restrict__ tfb2,
    const float* __restrict__ gbb1, const float* __restrict__ gbb2,
    const float* __restrict__ gab1, const float* __restrict__ gab2)
{
    extern __shared__ __align__(1024) char sm[];
    uint32_t smb = smem_u32(sm);
    int tid = threadIdx.x, wid = tid >> 5, lane = tid & 31;
    int q = lane & 3;
    int r0 = lane >> 2;
    int u0 = 8 * wid + 2 * q, u1 = u0 + 1;

    float tb1a = __ldg(&tfb1[u0]), tb1b = __ldg(&tfb1[u1]);
    float tb2a = __ldg(&tfb2[u0]), tb2b = __ldg(&tfb2[u1]);
    float gb1a = __ldg(&gbb1[u0]), gb1b = __ldg(&gbb1[u1]);
    float gb2a = __ldg(&gbb2[u0]), gb2b = __ldg(&gbb2[u1]);
    float ga1a = __ldg(&gab1[u0]), ga1b = __ldg(&gab1[u1]);
    float ga2a = __ldg(&gab2[u0]), ga2b = __ldg(&gab2[u1]);

    uint32_t xah = smb + SM_XAH, xal = smb + SM_XAL;
    uint32_t xbh = smb + SM_XBH, xbl = smb + SM_XBL;
    uint32_t x2h = smb + SM_X2H, x2l = smb + SM_X2L;
    char *XAHp = sm + SM_XAH, *XALp = sm + SM_XAL;
    char *XBHp = sm + SM_XBH, *XBLp = sm + SM_XBL;
    char *X2Hp = sm + SM_X2H, *X2Lp = sm + SM_X2L;
    int2* s_bai0 = (int2*)(sm + SM_BAI);

    const uint32_t* w0p = g_wfrag + (size_t)(0 * 256 + tid) * 8;
    const uint32_t* w1p = g_wfrag + (size_t)(3 * 256 + tid) * 8;
    const uint32_t* w2p = g_wfrag + (size_t)(7 * 256 + tid) * 8;

    int it = 0;
    for (int tile = blockIdx.x; tile < NTILE2; tile += gridDim.x, it ^= 1) {
        int e0 = tile * 64;
        int2* s_bai = s_bai0 + (it << 6);

        if (tid < 64) s_bai[tid] = __ldg(&bai[e0 + tid]);
        // stage agg tile (hi/lo, swizzled): 4 threads/row, 12 floats each
        {
            int r2 = tid >> 2, koff = 12 * (tid & 3);
            const float* srcp = g_agg + (size_t)(e0 + r2) * RBF_N + koff;
#pragma unroll
            for (int j = 0; j < 6; j++) {
                float2 v = __ldg((const float2*)(srcp + 2 * j));
                split_store(XAHp, XALp, (uint32_t)(r2 * 128 + (koff + 2 * j) * 2), v.x, v.y);
            }
        }
        __syncthreads();

        // ---- step A: tf (agg[48] -> 64 x2), consumes XA, writes XB ----
#pragma unroll
        for (int mp = 0; mp < 2; mp++) {
            int ma = 2 * mp;
            float D1a[4] = {0,0,0,0}, D2a[4] = {0,0,0,0};
            float D1b[4] = {0,0,0,0}, D2b[4] = {0,0,0,0};
            gemm_pair2<3>(D1a, D2a, D1b, D2b, xah, xal, ma, lane, w0p);
            EPI_A(2 * mp,     D1a, D2a);
            EPI_A(2 * mp + 1, D1b, D2b);
        }
        __syncthreads();

        // ---- step B: gb (bond -> 64 x2, + packed P gathers), writes X2 ----
#pragma unroll
        for (int mp = 0; mp < 2; mp++) {
            int ma = 2 * mp;
            float D1a[4] = {0,0,0,0}, D2a[4] = {0,0,0,0};
            float D1b[4] = {0,0,0,0}, D2b[4] = {0,0,0,0};
            gemm_pair2<4>(D1a, D2a, D1b, D2b, xbh, xbl, ma, lane, w1p);
            EPI_B(2 * mp,     D1a, D2a);
            EPI_B(2 * mp + 1, D1b, D2b);
        }
        __syncthreads();

        // ---- step C: ga (+ atom scatter), consumes X2; no trailing sync ----
#pragma unroll
        for (int mp = 0; mp < 2; mp++) {
            int ma = 2 * mp;
            float D1a[4] = {0,0,0,0}, D2a[4] = {0,0,0,0};
            float D1b[4] = {0,0,0,0}, D2b[4] = {0,0,0,0};
            gemm_pair2<4>(D1a, D2a, D1b, D2b, x2h, x2l, ma, lane, w2p);
            EPI_C(2 * mp,     D1a, D2a);
            EPI_C(2 * mp + 1, D1b, D2b);
        }
    }
}

// ---------------- readout ----------------
__global__ void k_readout(const float* __restrict__ wrW, const float* __restrict__ wrb,
                          const int* __restrict__ batch) {
    int idx = blockIdx.x * blockDim.x + threadIdx.x;
    if (idx >= A_N * U_N) return;
    int a = idx >> 6, u = idx & 63;
    const float* arow = g_atom + a * U_N;
    float s = __ldg(&wrb[u]);
#pragma unroll 8
    for (int k = 0; k < U_N; k++) s += arow[k] * __ldg(&wrW[k * U_N + u]);
    float gate = sigm(s);
    int g = __ldg(&batch[a]);
    atomicAdd(&g_num[g * U_N + u], gate * arow[u]);
    if (u == 0) atomicAdd(&g_cnt[g], 1.0f);
}

__global__ void k_final(const float* __restrict__ fW1, const float* __restrict__ fb1,
                        const float* __restrict__ fW2, const float* __restrict__ fb2,
                        float* __restrict__ out) {
    int g = blockIdx.x * blockDim.x + threadIdx.x;
    if (g >= G_N) return;
    float c = fmaxf(g_cnt[g], 1.0f);
    float vec[U_N];
#pragma unroll
    for (int u = 0; u < U_N; u++) vec[u] = g_num[g * U_N + u] / c;
    float o = __ldg(&fb2[0]);
    for (int j = 0; j < U_N; j++) {
        float h = __ldg(&fb1[j]);
#pragma unroll 8
        for (int k = 0; k < U_N; k++) h += vec[k] * __ldg(&fW1[k * U_N + j]);
        o += silu_f(h) * __ldg(&fW2[j]);
    }
    out[g] = o;
}

// ---------------- launcher ----------------
extern "C" void kernel_launch(void* const* d_in, const int* in_sizes, int n_in,
                              void* d_out, int out_size) {
    const int*    atom_types = (const int*)d_in[0];
    const int2*   bai        = (const int2*)d_in[1];
    const int2*   tbi        = (const int2*)d_in[2];
    const int*    batch      = (const int*)d_in[3];
    const float*  bond_rbf   = (const float*)d_in[4];
    const float4* three_b    = (const float4*)d_in[5];
    const float*  emb        = (const float*)d_in[6];
    const float*  bond_W     = (const float*)d_in[7];
    const float*  bond_b     = (const float*)d_in[8];
    const float*  tu_W       = (const float*)d_in[9];
    const float*  tu_b       = (const float*)d_in[10];
    const float*  tf_W1      = (const float*)d_in[11];
    const float*  tf_b1      = (const float*)d_in[12];
    const float*  tf_W2      = (const float*)d_in[13];
    const float*  tf_b2      = (const float*)d_in[14];
    const float*  gb_W1      = (const float*)d_in[15];
    const float*  gb_b1      = (const float*)d_in[16];
    const float*  gb_W2      = (const float*)d_in[17];
    const float*  gb_b2      = (const float*)d_in[18];
    const float*  ga_W1      = (const float*)d_in[19];
    const float*  ga_b1      = (const float*)d_in[20];
    const float*  ga_W2      = (const float*)d_in[21];
    const float*  ga_b2      = (const float*)d_in[22];
    const float*  wr_W       = (const float*)d_in[23];
    const float*  wr_b       = (const float*)d_in[24];
    const float*  f_W1       = (const float*)d_in[25];
    const float*  f_b1       = (const float*)d_in[26];
    const float*  f_W2       = (const float*)d_in[27];
    const float*  f_b2       = (const float*)d_in[28];
    float* out = (float*)d_out;

    cudaFuncSetAttribute(k_bond_tc, cudaFuncAttributeMaxDynamicSharedMemorySize, SM_TOT);

    // launch 0: all init
    k_init_mega<<<NB_INIT, 256>>>(atom_types, emb, bond_rbf, bond_W, bond_b);
    // launch 1: iter-0 prep (tu + P + wprep)
    k_prep_mega<<<NB_TU + NB_P + 3, 256>>>(tu_W, tu_b, gb_W1, gb_W2, tf_W1, tf_W2, ga_W1, ga_W2);
    // launch 2: iter-0 triples (atomic scatter)
    k_triples<<<(T_N * 12 + 255) / 256, 256>>>(three_b, tbi, bai);
    // launch 3: iter-0 bond kernel  <-- ncu capture lands here
    k_bond_tc<<<592, 256, SM_TOT>>>(bai, tf_b1, tf_b2, gb_b1, gb_b2, ga_b1, ga_b2);

    // CSR build for iters 1,2
    k_count<<<(T_N + 255) / 256, 256>>>(tbi);
    k_scanA<<<NBLK_E, 256>>>();
    k_scanB<<<1, 256>>>();
    k_scanC<<<NBLK_E, 256>>>();
    k_fill<<<(T_N + 255) / 256, 256>>>(tbi, bai);

    for (int i = 1; i < 3; i++) {
        const float* tuW  = tu_W  + i * U_N * RBF_N;
        const float* tub  = tu_b  + i * RBF_N;
        const float* tfW1 = tf_W1 + i * RBF_N * U_N;
        const float* tfb1 = tf_b1 + i * U_N;
        const float* tfW2 = tf_W2 + i * RBF_N * U_N;
        const float* tfb2 = tf_b2 + i * U_N;
        const float* gbW1 = gb_W1 + i * 3 * U_N * U_N;
        const float* gbb1 = gb_b1 + i * U_N;
        const float* gbW2 = gb_W2 + i * 3 * U_N * U_N;
        const float* gbb2 = gb_b2 + i * U_N;
        const float* gaW1 = ga_W1 + i * U_N * U_N;
        const float* gab1 = ga_b1 + i * U_N;
        const float* gaW2 = ga_W2 + i * U_N * U_N;
        const float* gab2 = ga_b2 + i * U_N;

        k_tu<<<NB_TU, 256>>>(tuW, tub);
        k_agg<<<(E_N * 4 + 255) / 256, 256>>>(three_b);
        k_P<<<NB_P, 256>>>(gbW1, gbW2);
        k_wprep<<<3, 256>>>(tfW1, tfW2,
                            gbW1 + 128 * U_N, gbW2 + 128 * U_N,
                            gaW1, gaW2);
        k_bond_tc<<<592, 256, SM_TOT>>>(bai, tfb1, tfb2, gbb1, gbb2, gab1, gab2);
    }

    k_readout<<<NB_P, 256>>>(wr_W, wr_b, batch);
    k_final<<<1, 512>>>(f_W1, f_b1, f_W2, f_b2, out);
}

// round 17
// speedup vs baseline: 1.0844x; 1.0844x over previous
#include <cuda_runtime.h>
#include <cuda_bf16.h>
#include <cstdint>

#define A_N 50000
#define E_N 1200000
#define T_N 2000000
#define G_N 500
#define U_N 64
#define RBF_N 48
#define NTILE2 (E_N / 64)            // 18750 tiles of 64 bonds
#define NBLK_E ((E_N + 255) / 256)   // 4688

// ---------------- scratch (device globals; no allocation allowed) ----------------
__device__ float g_atom[A_N * U_N];
__device__ float g_bond[E_N * U_N];
__device__ float g_tuw[A_N * RBF_N];
__device__ float g_agg[E_N * RBF_N];
__device__ float g_Psrc[A_N * 128];   // interleaved {P1s,P2s} per u
__device__ float g_Pdst[A_N * 128];   // interleaved {P1d,P2d} per u
__device__ float g_num[G_N * U_N];
__device__ float g_cnt[G_N];
// W fragments: [ks_global 0..10][tid 0..255][8 words]; base: tf=0, gb=3, ga=7
__device__ uint32_t g_wfrag[11 * 256 * 8];
// CSR for triples grouped by bond (static across the 3 blocks)
__device__ int  g_deg[E_N];
__device__ int  g_basei[E_N];
__device__ int  g_cur[E_N];
__device__ int  g_blks[NBLK_E];
__device__ int2 g_csr[T_N];          // {triple_idx, end_atom}

__device__ __forceinline__ float sigm(float x) { return 1.0f / (1.0f + __expf(-x)); }
__device__ __forceinline__ float silu_f(float x) { return x * sigm(x); }

__device__ __forceinline__ void red_add_v2(float* addr, float a, float b) {
    asm volatile("red.global.add.v2.f32 [%0], {%1,%2};"
                 :: "l"(addr), "f"(a), "f"(b) : "memory");
}

// ---------------- warp-MMA helpers ----------------
__device__ __forceinline__ uint32_t smem_u32(const void* p) {
    uint32_t a;
    asm("{ .reg .u64 t; cvta.to.shared.u64 t, %1; cvt.u32.u64 %0, t; }" : "=r"(a) : "l"(p));
    return a;
}
#define SWZ(x) ((x) ^ (((x) >> 3) & 0x70))

__device__ __forceinline__ void ldsm4(uint32_t* r, uint32_t a) {
    asm volatile("ldmatrix.sync.aligned.m8n8.x4.shared.b16 {%0,%1,%2,%3}, [%4];"
        : "=r"(r[0]), "=r"(r[1]), "=r"(r[2]), "=r"(r[3]) : "r"(a));
}
__device__ __forceinline__ void mma_bf16(float* d, const uint32_t* a, const uint32_t* b) {
    asm volatile("mma.sync.aligned.m16n8k16.row.col.f32.bf16.bf16.f32 "
        "{%0,%1,%2,%3}, {%4,%5,%6,%7}, {%8,%9}, {%0,%1,%2,%3};"
        : "+f"(d[0]), "+f"(d[1]), "+f"(d[2]), "+f"(d[3])
        : "r"(a[0]), "r"(a[1]), "r"(a[2]), "r"(a[3]), "r"(b[0]), "r"(b[1]));
}

__device__ __forceinline__ void split2(float x, float y, uint32_t& hw, uint32_t& lw) {
    __nv_bfloat16 hx = __float2bfloat16(x), hy = __float2bfloat16(y);
    __nv_bfloat16 lx = __float2bfloat16(x - __bfloat162float(hx));
    __nv_bfloat16 ly = __float2bfloat16(y - __bfloat162float(hy));
    __nv_bfloat162 h2 = __halves2bfloat162(hx, hy), l2 = __halves2bfloat162(lx, ly);
    hw = *(uint32_t*)&h2; lw = *(uint32_t*)&l2;
}
__device__ __forceinline__ void split_store(char* bh, char* bl, uint32_t byteoff, float x, float y) {
    uint32_t hw, lw;
    split2(x, y, hw, lw);
    uint32_t so = SWZ(byteoff);
    *(uint32_t*)(bh + so) = hw;
    *(uint32_t*)(bl + so) = lw;
}

// MMA for a pair of 16-row m-tiles; W streamed per-kstep from global (L1-resident table).
template<int NKS>
__device__ __forceinline__ void gemm_pair2(
    float* D1a, float* D2a, float* D1b, float* D2b,
    uint32_t xh, uint32_t xl, int ma, int lane,
    const uint32_t* __restrict__ wptr)
{
    int mtx = lane >> 3, rr = lane & 7;
    int rowa = 16 * ma + rr + 8 * (mtx & 1);
    int rowb = rowa + 16;
    int cb = (mtx >> 1) * 16;
#pragma unroll
    for (int ks = 0; ks < NKS; ks++) {
        uint4 wa = __ldg((const uint4*)(wptr + ks * 2048));
        uint4 wb = __ldg((const uint4*)(wptr + ks * 2048 + 4));
        uint32_t W1h[2] = {wa.x, wa.y}, W1l[2] = {wa.z, wa.w};
        uint32_t W2h[2] = {wb.x, wb.y}, W2l[2] = {wb.z, wb.w};
        uint32_t oa = SWZ((uint32_t)(rowa * 128 + ks * 32 + cb));
        uint32_t ob = SWZ((uint32_t)(rowb * 128 + ks * 32 + cb));
        uint32_t Aha[4], Ala[4], Ahb[4], Alb[4];
        ldsm4(Aha, xh + oa); ldsm4(Ahb, xh + ob);
        ldsm4(Ala, xl + oa); ldsm4(Alb, xl + ob);
        mma_bf16(D1a, Aha, W1h); mma_bf16(D1b, Ahb, W1h);
        mma_bf16(D2a, Aha, W2h); mma_bf16(D2b, Ahb, W2h);
        mma_bf16(D1a, Ala, W1h); mma_bf16(D1b, Alb, W1h);
        mma_bf16(D2a, Ala, W2h); mma_bf16(D2b, Alb, W2h);
        mma_bf16(D1a, Aha, W1l); mma_bf16(D1b, Ahb, W1l);
        mma_bf16(D2a, Aha, W2l); mma_bf16(D2b, Ahb, W2l);
    }
}

// ---------------- mega init (NO agg zeroing — k_agg fully overwrites) ----------------
#define NB_ATOM  ((A_N * U_N + 255) / 256)
#define NB_BOND  ((E_N * U_N + 255) / 256)
#define NB_INIT  (NB_ATOM + NB_BOND + NBLK_E + 1)

__global__ void k_init_mega(const int* __restrict__ types, const float* __restrict__ emb,
                            const float* __restrict__ rbf, const float* __restrict__ W,
                            const float* __restrict__ b) {
    int blk = blockIdx.x;
    if (blk < NB_ATOM) {
        int idx = blk * 256 + threadIdx.x;
        if (idx >= A_N * U_N) return;
        int a = idx >> 6, u = idx & 63;
        g_atom[idx] = __ldg(&emb[__ldg(&types[a]) * U_N + u]);
        return;
    }
    blk -= NB_ATOM;
    if (blk < NB_BOND) {
        int idx = blk * 256 + threadIdx.x;
        if (idx >= E_N * U_N) return;
        int e = idx >> 6, u = idx & 63;
        float v = __ldg(&b[u]);
        v += __ldg(&rbf[e * 3 + 0]) * __ldg(&W[0 * U_N + u]);
        v += __ldg(&rbf[e * 3 + 1]) * __ldg(&W[1 * U_N + u]);
        v += __ldg(&rbf[e * 3 + 2]) * __ldg(&W[2 * U_N + u]);
        g_bond[idx] = silu_f(v);
        return;
    }
    blk -= NB_BOND;
    if (blk < NBLK_E) {
        int idx = blk * 256 + threadIdx.x;
        if (idx < E_N) g_deg[idx] = 0;
        return;
    }
    for (int idx = threadIdx.x; idx < G_N * U_N; idx += 256) g_num[idx] = 0.f;
    for (int idx = threadIdx.x; idx < G_N; idx += 256) g_cnt[idx] = 0.f;
}

// ---------------- prep bodies ----------------
__device__ __forceinline__ void tu_body(int idx, const float* tuW, const float* tub) {
    if (idx >= A_N * RBF_N) return;
    int a = idx / RBF_N, j = idx - a * RBF_N;
    const float* arow = g_atom + a * U_N;
    float s = __ldg(&tub[j]);
#pragma unroll 8
    for (int k = 0; k < U_N; k++) s += arow[k] * __ldg(&tuW[k * RBF_N + j]);
    g_tuw[idx] = sigm(s);
}
__device__ __forceinline__ void P_body(int idx, const float* W1, const float* W2) {
    if (idx >= A_N * U_N) return;
    int a = idx >> 6, u = idx & 63;
    const float* arow = g_atom + a * U_N;
    float s0 = 0.f, s1 = 0.f, s2 = 0.f, s3 = 0.f;
#pragma unroll 8
    for (int k = 0; k < U_N; k++) {
        float av = arow[k];
        s0 += av * __ldg(&W1[k * U_N + u]);
        s1 += av * __ldg(&W1[(U_N + k) * U_N + u]);
        s2 += av * __ldg(&W2[k * U_N + u]);
        s3 += av * __ldg(&W2[(U_N + k) * U_N + u]);
    }
    g_Psrc[a * 128 + 2 * u]     = s0;
    g_Psrc[a * 128 + 2 * u + 1] = s2;
    g_Pdst[a * 128 + 2 * u]     = s1;
    g_Pdst[a * 128 + 2 * u + 1] = s3;
}
__device__ __forceinline__ void wprep_body(int s, int tid,
                        const float* tfW1, const float* tfW2,
                        const float* gbW1c, const float* gbW2c,
                        const float* gaW1, const float* gaW2) {
    int wid = tid >> 5, lane = tid & 31;
    int q = lane & 3, nf = lane >> 2;
    int n_abs = 8 * wid + nf;
    const float *W1, *W2; int nks, base;
    if (s == 0)      { W1 = tfW1;  W2 = tfW2;  nks = 3; base = 0; }
    else if (s == 1) { W1 = gbW1c; W2 = gbW2c; nks = 4; base = 3; }
    else             { W1 = gaW1;  W2 = gaW2;  nks = 4; base = 7; }
    for (int m = 0; m < 2; m++) {
        const float* W = m ? W2 : W1;
        for (int ks = 0; ks < nks; ks++)
            for (int R = 0; R < 2; R++) {
                int k0 = 16 * ks + 2 * q + 8 * R;
                float x = __ldg(&W[k0 * 64 + n_abs]);
                float y = __ldg(&W[(k0 + 1) * 64 + n_abs]);
                uint32_t hw, lw;
                split2(x, y, hw, lw);
                uint32_t* slot = g_wfrag + ((base + ks) * 256 + tid) * 8;
                slot[m * 4 + R]     = hw;
                slot[m * 4 + 2 + R] = lw;
            }
    }
}

#define NB_TU ((A_N * RBF_N + 255) / 256)
#define NB_P  ((A_N * U_N + 255) / 256)

// per-iteration prep: tu | P | wprep in one launch
__global__ void k_prep_mega(const float* __restrict__ tuW, const float* __restrict__ tub,
                            const float* __restrict__ gbW1, const float* __restrict__ gbW2,
                            const float* __restrict__ tfW1, const float* __restrict__ tfW2,
                            const float* __restrict__ gaW1, const float* __restrict__ gaW2) {
    int blk = blockIdx.x;
    if (blk < NB_TU) { tu_body(blk * 256 + threadIdx.x, tuW, tub); return; }
    blk -= NB_TU;
    if (blk < NB_P) { P_body(blk * 256 + threadIdx.x, gbW1, gbW2); return; }
    blk -= NB_P;
    wprep_body(blk, threadIdx.x, tfW1, tfW2, gbW1 + 128 * U_N, gbW2 + 128 * U_N, gaW1, gaW2);
}

// ---------------- CSR build (front of launch; topology static) ----------------
__global__ void k_count(const int2* __restrict__ tbi) {
    int t = blockIdx.x * blockDim.x + threadIdx.x;
    if (t < T_N) atomicAdd(&g_deg[__ldg(&tbi[t]).x], 1);
}
__global__ void k_scanA() {
    __shared__ int ssum[256];
    int idx = blockIdx.x * 256 + threadIdx.x;
    int v = (idx < E_N) ? g_deg[idx] : 0;
    ssum[threadIdx.x] = v;
    __syncthreads();
    for (int off = 128; off > 0; off >>= 1) {
        if (threadIdx.x < off) ssum[threadIdx.x] += ssum[threadIdx.x + off];
        __syncthreads();
    }
    if (threadIdx.x == 0) g_blks[blockIdx.x] = ssum[0];
}
__global__ void k_scanB() {
    __shared__ int wsum[8];
    const int CH = (NBLK_E + 255) / 256;
    int tid = threadIdx.x, lane = tid & 31, wid = tid >> 5;
    int vals[CH];
    int s = 0;
#pragma unroll
    for (int j = 0; j < CH; j++) {
        int i = tid * CH + j;
        vals[j] = (i < NBLK_E) ? g_blks[i] : 0;
        s += vals[j];
    }
    int incl = s;
    for (int off = 1; off < 32; off <<= 1) {
        int n = __shfl_up_sync(0xFFFFFFFFu, incl, off);
        if (lane >= off) incl += n;
    }
    if (lane == 31) wsum[wid] = incl;
    __syncthreads();
    int woff = 0;
    for (int w = 0; w < 8; w++) { if (w < wid) woff += wsum[w]; }
    int run = woff + incl - s;
#pragma unroll
    for (int j = 0; j < CH; j++) {
        int i = tid * CH + j;
        if (i < NBLK_E) { g_blks[i] = run; }
        run += vals[j];
    }
}
__global__ void k_scanC() {
    __shared__ int wsum[8];
    int idx = blockIdx.x * 256 + threadIdx.x;
    int tid = threadIdx.x, lane = tid & 31, wid = tid >> 5;
    int v = (idx < E_N) ? g_deg[idx] : 0;
    int incl = v;
    for (int off = 1; off < 32; off <<= 1) {
        int n = __shfl_up_sync(0xFFFFFFFFu, incl, off);
        if (lane >= off) incl += n;
    }
    if (lane == 31) wsum[wid] = incl;
    __syncthreads();
    int woff = 0;
    for (int w = 0; w < 8; w++) { if (w < wid) woff += wsum[w]; }
    if (idx < E_N) {
        g_basei[idx] = g_blks[blockIdx.x] + woff + incl - v;
        g_cur[idx] = 0;
    }
}
__global__ void k_fill(const int2* __restrict__ tbi, const int2* __restrict__ bai) {
    int t = blockIdx.x * blockDim.x + threadIdx.x;
    if (t >= T_N) return;
    int2 ti = __ldg(&tbi[t]);
    int ea = __ldg(&bai[ti.y]).y;
    int pos = g_basei[ti.x] + atomicAdd(&g_cur[ti.x], 1);
    g_csr[pos] = make_int2(t, ea);
}

// gather triple segment-sum: 4 threads per bond (all 3 iterations)
__global__ void k_agg(const float4* __restrict__ tb) {
    int idx = blockIdx.x * blockDim.x + threadIdx.x;
    if (idx >= E_N * 4) return;
    int e = idx >> 2, q = idx & 3;
    int b0 = __ldg(&g_basei[e]);
    int b1 = (e == E_N - 1) ? T_N : __ldg(&g_basei[e + 1]);
    float4 a0 = make_float4(0.f, 0.f, 0.f, 0.f), a1 = a0, a2 = a0;
    for (int p = b0; p < b1; p++) {
        int2 te = __ldg(&g_csr[p]);
        const float4* tvp = tb + (size_t)te.x * 12 + q * 3;
        const float4* wvp = (const float4*)(g_tuw + (size_t)te.y * RBF_N + q * 12);
        float4 t0 = __ldg(tvp),     w0 = __ldg(wvp);
        float4 t1 = __ldg(tvp + 1), w1 = __ldg(wvp + 1);
        float4 t2 = __ldg(tvp + 2), w2 = __ldg(wvp + 2);
        a0.x += t0.x * w0.x; a0.y += t0.y * w0.y; a0.z += t0.z * w0.z; a0.w += t0.w * w0.w;
        a1.x += t1.x * w1.x; a1.y += t1.y * w1.y; a1.z += t1.z * w1.z; a1.w += t1.w * w1.w;
        a2.x += t2.x * w2.x; a2.y += t2.y * w2.y; a2.z += t2.z * w2.z; a2.w += t2.w * w2.w;
    }
    float4* dst = (float4*)(g_agg + (size_t)e * RBF_N + q * 12);
    dst[0] = a0; dst[1] = a1; dst[2] = a2;
}

// ---------------- tensor-core fused bond kernel: M=64 tiles, 3 CTAs/SM (R14 exact) ----
#define SM_XAH 0
#define SM_XAL 8192
#define SM_XBH 16384
#define SM_XBL 24576
#define SM_X2H 32768
#define SM_X2L 40960
#define SM_BAI 49152
#define SM_TOT (49152 + 1024)

#define EPI_A(M, D1, D2) { \
    int rA = 16 * (M) + r0, rB = rA + 8; \
    int eA = e0 + rA, eB = e0 + rB; \
    float2 v0 = __ldg((const float2*)(g_bond + (size_t)eA * 64 + u0)); \
    float2 v1 = __ldg((const float2*)(g_bond + (size_t)eB * 64 + u0)); \
    nb[M][0] = v0.x + silu_f((D1)[0] + tb1a) * sigm((D2)[0] + tb2a); \
    nb[M][1] = v0.y + silu_f((D1)[1] + tb1b) * sigm((D2)[1] + tb2b); \
    nb[M][2] = v1.x + silu_f((D1)[2] + tb1a) * sigm((D2)[2] + tb2a); \
    nb[M][3] = v1.y + silu_f((D1)[3] + tb1b) * sigm((D2)[3] + tb2b); \
    split_store(XBHp, XBLp, (uint32_t)(rA * 128 + u0 * 2), nb[M][0], nb[M][1]); \
    split_store(XBHp, XBLp, (uint32_t)(rB * 128 + u0 * 2), nb[M][2], nb[M][3]); \
}

#define EPI_B(M, D1, D2) { \
    int rA = 16 * (M) + r0, rB = rA + 8; \
    int eA = e0 + rA, eB = e0 + rB; \
    int2 iA = s_bai[rA]; int2 iB = s_bai[rB]; \
    float4 psA = __ldg((const float4*)(g_Psrc + (size_t)iA.x * 128 + 2 * u0)); \
    float4 pdA = __ldg((const float4*)(g_Pdst + (size_t)iA.y * 128 + 2 * u0)); \
    float4 psB = __ldg((const float4*)(g_Psrc + (size_t)iB.x * 128 + 2 * u0)); \
    float4 pdB = __ldg((const float4*)(g_Pdst + (size_t)iB.y * 128 + 2 * u0)); \
    nb[M][0] += silu_f((D1)[0] + gb1a + psA.x + pdA.x) * sigm((D2)[0] + gb2a + psA.y + pdA.y); \
    nb[M][1] += silu_f((D1)[1] + gb1b + psA.z + pdA.z) * sigm((D2)[1] + gb2b + psA.w + pdA.w); \
    nb[M][2] += silu_f((D1)[2] + gb1a + psB.x + pdB.x) * sigm((D2)[2] + gb2a + psB.y + pdB.y); \
    nb[M][3] += silu_f((D1)[3] + gb1b + psB.z + pdB.z) * sigm((D2)[3] + gb2b + psB.w + pdB.w); \
    *(float2*)(g_bond + (size_t)eA * 64 + u0) = make_float2(nb[M][0], nb[M][1]); \
    *(float2*)(g_bond + (size_t)eB * 64 + u0) = make_float2(nb[M][2], nb[M][3]); \
    split_store(X2Hp, X2Lp, (uint32_t)(rA * 128 + u0 * 2), nb[M][0], nb[M][1]); \
    split_store(X2Hp, X2Lp, (uint32_t)(rB * 128 + u0 * 2), nb[M][2], nb[M][3]); \
}

#define EPI_C(M, D1, D2) { \
    int rA = 16 * (M) + r0, rB = rA + 8; \
    int dA = s_bai[rA].y, dB = s_bai[rB].y; \
    float m0 = silu_f((D1)[0] + ga1a) * sigm((D2)[0] + ga2a); \
    float m1 = silu_f((D1)[1] + ga1b) * sigm((D2)[1] + ga2b); \
    float m2 = silu_f((D1)[2] + ga1a) * sigm((D2)[2] + ga2a); \
    float m3 = silu_f((D1)[3] + ga1b) * sigm((D2)[3] + ga2b); \
    red_add_v2(g_atom + (size_t)dA * 64 + u0, m0, m1); \
    red_add_v2(g_atom + (size_t)dB * 64 + u0, m2, m3); \
}

__global__ __launch_bounds__(256, 3) void k_bond_tc(
    const int2* __restrict__ bai,
    const float* __restrict__ tfb1, const float* __restrict__ tfb2,
    const float* __restrict__ gbb1, const float* __restrict__ gbb2,
    const float* __restrict__ gab1, const float* __restrict__ gab2)
{
    extern __shared__ __align__(1024) char sm[];
    uint32_t smb = smem_u32(sm);
    int tid = threadIdx.x, wid = tid >> 5, lane = tid & 31;
    int q = lane & 3;
    int r0 = lane >> 2;
    int u0 = 8 * wid + 2 * q, u1 = u0 + 1;

    float tb1a = __ldg(&tfb1[u0]), tb1b = __ldg(&tfb1[u1]);
    float tb2a = __ldg(&tfb2[u0]), tb2b = __ldg(&tfb2[u1]);
    float gb1a = __ldg(&gbb1[u0]), gb1b = __ldg(&gbb1[u1]);
    float gb2a = __ldg(&gbb2[u0]), gb2b = __ldg(&gbb2[u1]);
    float ga1a = __ldg(&gab1[u0]), ga1b = __ldg(&gab1[u1]);
    float ga2a = __ldg(&gab2[u0]), ga2b = __ldg(&gab2[u1]);

    uint32_t xah = smb + SM_XAH, xal = smb + SM_XAL;
    uint32_t xbh = smb + SM_XBH, xbl = smb + SM_XBL;
    uint32_t x2h = smb + SM_X2H, x2l = smb + SM_X2L;
    char *XAHp = sm + SM_XAH, *XALp = sm + SM_XAL;
    char *XBHp = sm + SM_XBH, *XBLp = sm + SM_XBL;
    char *X2Hp = sm + SM_X2H, *X2Lp = sm + SM_X2L;
    int2* s_bai0 = (int2*)(sm + SM_BAI);

    const uint32_t* w0p = g_wfrag + (size_t)(0 * 256 + tid) * 8;
    const uint32_t* w1p = g_wfrag + (size_t)(3 * 256 + tid) * 8;
    const uint32_t* w2p = g_wfrag + (size_t)(7 * 256 + tid) * 8;

    int it = 0;
    for (int tile = blockIdx.x; tile < NTILE2; tile += gridDim.x, it ^= 1) {
        int e0 = tile * 64;
        int2* s_bai = s_bai0 + (it << 6);

        if (tid < 64) s_bai[tid] = __ldg(&bai[e0 + tid]);
        // stage agg tile (hi/lo, swizzled): 4 threads/row, 12 floats each
        {
            int r2 = tid >> 2, koff = 12 * (tid & 3);
            const float* srcp = g_agg + (size_t)(e0 + r2) * RBF_N + koff;
#pragma unroll
            for (int j = 0; j < 6; j++) {
                float2 v = __ldg((const float2*)(srcp + 2 * j));
                split_store(XAHp, XALp, (uint32_t)(r2 * 128 + (koff + 2 * j) * 2), v.x, v.y);
            }
        }
        __syncthreads();

        float nb[4][4];

        // ---- step A: tf (agg[48] -> 64 x2), consumes XA, writes XB ----
#pragma unroll
        for (int mp = 0; mp < 2; mp++) {
            int ma = 2 * mp;
            float D1a[4] = {0,0,0,0}, D2a[4] = {0,0,0,0};
            float D1b[4] = {0,0,0,0}, D2b[4] = {0,0,0,0};
            gemm_pair2<3>(D1a, D2a, D1b, D2b, xah, xal, ma, lane, w0p);
            EPI_A(2 * mp,     D1a, D2a);
            EPI_A(2 * mp + 1, D1b, D2b);
        }
        __syncthreads();

        // ---- step B: gb (bond -> 64 x2, + packed P gathers), writes X2 ----
#pragma unroll
        for (int mp = 0; mp < 2; mp++) {
            int ma = 2 * mp;
            float D1a[4] = {0,0,0,0}, D2a[4] = {0,0,0,0};
            float D1b[4] = {0,0,0,0}, D2b[4] = {0,0,0,0};
            gemm_pair2<4>(D1a, D2a, D1b, D2b, xbh, xbl, ma, lane, w1p);
            EPI_B(2 * mp,     D1a, D2a);
            EPI_B(2 * mp + 1, D1b, D2b);
        }
        __syncthreads();

        // ---- step C: ga (+ atom scatter), consumes X2; no trailing sync ----
#pragma unroll
        for (int mp = 0; mp < 2; mp++) {
            int ma = 2 * mp;
            float D1a[4] = {0,0,0,0}, D2a[4] = {0,0,0,0};
            float D1b[4] = {0,0,0,0}, D2b[4] = {0,0,0,0};
            gemm_pair2<4>(D1a, D2a, D1b, D2b, x2h, x2l, ma, lane, w2p);
            EPI_C(2 * mp,     D1a, D2a);
            EPI_C(2 * mp + 1, D1b, D2b);
        }
    }
}

// ---------------- readout ----------------
__global__ void k_readout(const float* __restrict__ wrW, const float* __restrict__ wrb,
                          const int* __restrict__ batch) {
    int idx = blockIdx.x * blockDim.x + threadIdx.x;
    if (idx >= A_N * U_N) return;
    int a = idx >> 6, u = idx & 63;
    const float* arow = g_atom + a * U_N;
    float s = __ldg(&wrb[u]);
#pragma unroll 8
    for (int k = 0; k < U_N; k++) s += arow[k] * __ldg(&wrW[k * U_N + u]);
    float gate = sigm(s);
    int g = __ldg(&batch[a]);
    atomicAdd(&g_num[g * U_N + u], gate * arow[u]);
    if (u == 0) atomicAdd(&g_cnt[g], 1.0f);
}

__global__ void k_final(const float* __restrict__ fW1, const float* __restrict__ fb1,
                        const float* __restrict__ fW2, const float* __restrict__ fb2,
                        float* __restrict__ out) {
    int g = blockIdx.x * blockDim.x + threadIdx.x;
    if (g >= G_N) return;
    float c = fmaxf(g_cnt[g], 1.0f);
    float vec[U_N];
#pragma unroll
    for (int u = 0; u < U_N; u++) vec[u] = g_num[g * U_N + u] / c;
    float o = __ldg(&fb2[0]);
    for (int j = 0; j < U_N; j++) {
        float h = __ldg(&fb1[j]);
#pragma unroll 8
        for (int k = 0; k < U_N; k++) h += vec[k] * __ldg(&fW1[k * U_N + j]);
        o += silu_f(h) * __ldg(&fW2[j]);
    }
    out[g] = o;
}

// ---------------- launcher ----------------
extern "C" void kernel_launch(void* const* d_in, const int* in_sizes, int n_in,
                              void* d_out, int out_size) {
    const int*    atom_types = (const int*)d_in[0];
    const int2*   bai        = (const int2*)d_in[1];
    const int2*   tbi        = (const int2*)d_in[2];
    const int*    batch      = (const int*)d_in[3];
    const float*  bond_rbf   = (const float*)d_in[4];
    const float4* three_b    = (const float4*)d_in[5];
    const float*  emb        = (const float*)d_in[6];
    const float*  bond_W     = (const float*)d_in[7];
    const float*  bond_b     = (const float*)d_in[8];
    const float*  tu_W       = (const float*)d_in[9];
    const float*  tu_b       = (const float*)d_in[10];
    const float*  tf_W1      = (const float*)d_in[11];
    const float*  tf_b1      = (const float*)d_in[12];
    const float*  tf_W2      = (const float*)d_in[13];
    const float*  tf_b2      = (const float*)d_in[14];
    const float*  gb_W1      = (const float*)d_in[15];
    const float*  gb_b1      = (const float*)d_in[16];
    const float*  gb_W2      = (const float*)d_in[17];
    const float*  gb_b2      = (const float*)d_in[18];
    const float*  ga_W1      = (const float*)d_in[19];
    const float*  ga_b1      = (const float*)d_in[20];
    const float*  ga_W2      = (const float*)d_in[21];
    const float*  ga_b2      = (const float*)d_in[22];
    const float*  wr_W       = (const float*)d_in[23];
    const float*  wr_b       = (const float*)d_in[24];
    const float*  f_W1       = (const float*)d_in[25];
    const float*  f_b1       = (const float*)d_in[26];
    const float*  f_W2       = (const float*)d_in[27];
    const float*  f_b2       = (const float*)d_in[28];
    float* out = (float*)d_out;

    cudaFuncSetAttribute(k_bond_tc, cudaFuncAttributeMaxDynamicSharedMemorySize, SM_TOT);

    // init (atoms, bonds, small, deg) — no agg zeroing needed
    k_init_mega<<<NB_INIT, 256>>>(atom_types, emb, bond_rbf, bond_W, bond_b);
    // CSR build (depends only on static topology)
    k_count<<<(T_N + 255) / 256, 256>>>(tbi);
    k_scanA<<<NBLK_E, 256>>>();
    k_scanB<<<1, 256>>>();
    k_scanC<<<NBLK_E, 256>>>();
    k_fill<<<(T_N + 255) / 256, 256>>>(tbi, bai);

    for (int i = 0; i < 3; i++) {
        const float* tuW  = tu_W  + i * U_N * RBF_N;
        const float* tub  = tu_b  + i * RBF_N;
        const float* tfW1 = tf_W1 + i * RBF_N * U_N;
        const float* tfb1 = tf_b1 + i * U_N;
        const float* tfW2 = tf_W2 + i * RBF_N * U_N;
        const float* tfb2 = tf_b2 + i * U_N;
        const float* gbW1 = gb_W1 + i * 3 * U_N * U_N;
        const float* gbb1 = gb_b1 + i * U_N;
        const float* gbW2 = gb_W2 + i * 3 * U_N * U_N;
        const float* gbb2 = gb_b2 + i * U_N;
        const float* gaW1 = ga_W1 + i * U_N * U_N;
        const float* gab1 = ga_b1 + i * U_N;
        const float* gaW2 = ga_W2 + i * U_N * U_N;
        const float* gab2 = ga_b2 + i * U_N;

        k_prep_mega<<<NB_TU + NB_P + 3, 256>>>(tuW, tub, gbW1, gbW2, tfW1, tfW2, gaW1, gaW2);
        k_agg<<<(E_N * 4 + 255) / 256, 256>>>(three_b);
        k_bond_tc<<<444, 256, SM_TOT>>>(bai, tfb1, tfb2, gbb1, gbb2, gab1, gab2);
    }

    k_readout<<<NB_P, 256>>>(wr_W, wr_b, batch);
    k_final<<<1, 512>>>(f_W1, f_b1, f_W2, f_b2, out);
}